// round 2
// baseline (speedup 1.0000x reference)
#include <cuda_runtime.h>
#include <math.h>

#define TOK 512
#define DMODEL 512
#define FF 2048
#define DN 128
#define DH 256
#define DH2 512
#define LN_EPS 1e-5f

// ---------------- scratch (no allocation allowed) ----------------
__device__ float g_acts[TOK * FF];     // 4 MB
__device__ float g_nvproj[FF * DH];    // 2 MB
__device__ float g_agg[TOK * DH];
__device__ float g_r[TOK * DH];
__device__ float g_r2[TOK * DH2];

__device__ __forceinline__ float gelu_exact(float x) {
    return 0.5f * x * (1.0f + erff(x * 0.70710678118654752440f));
}

// ---------------- generic tiled GEMM: C = act(A[M,K] @ B[N,K]^T + bias) ----
// BM=64, BN=128, BK=32, 256 threads, thread tile 8x4.
// MODE selects source/dest scratch buffers (device globals, no host symbol lookup):
//   0: A=x(param), C=g_acts      (gelu)
//   1: A=g_nvproj? no — A=neuron_vecs(param), C=g_nvproj
//   2: A=g_r,  C=g_r2            (gelu+bias)
//   3: A=g_r2, C=out(param)      (bias)
template <bool GELU, bool BIAS>
__global__ void __launch_bounds__(256) gemm_tn(
    const float* __restrict__ A, int lda,
    const float* __restrict__ B, int ldb,
    const float* __restrict__ bias,
    float* __restrict__ C, int ldc,
    int K)
{
    constexpr int BM = 64, BN = 128, BK = 32;
    __shared__ float sA[BK][BM + 2];
    __shared__ float sB[BK][BN + 2];
    int tid = threadIdx.x;
    int lane = tid & 31, wid = tid >> 5;
    int bm = blockIdx.x * BM, bn = blockIdx.y * BN;

    float acc[8][4];
#pragma unroll
    for (int i = 0; i < 8; i++)
#pragma unroll
        for (int u = 0; u < 4; u++) acc[i][u] = 0.f;

    for (int k0 = 0; k0 < K; k0 += BK) {
#pragma unroll
        for (int r = 0; r < 8; r++) {
            int m = wid + 8 * r;
            sA[lane][m] = A[(size_t)(bm + m) * lda + k0 + lane];
        }
#pragma unroll
        for (int r = 0; r < 16; r++) {
            int n = wid + 8 * r;
            sB[lane][n] = B[(size_t)(bn + n) * ldb + k0 + lane];
        }
        __syncthreads();
#pragma unroll
        for (int kk = 0; kk < BK; kk++) {
            float a[8], b[4];
#pragma unroll
            for (int i = 0; i < 8; i++) a[i] = sA[kk][wid * 8 + i];
#pragma unroll
            for (int u = 0; u < 4; u++) b[u] = sB[kk][lane + 32 * u];
#pragma unroll
            for (int i = 0; i < 8; i++)
#pragma unroll
                for (int u = 0; u < 4; u++) acc[i][u] += a[i] * b[u];
        }
        __syncthreads();
    }
#pragma unroll
    for (int i = 0; i < 8; i++) {
        int m = bm + wid * 8 + i;
#pragma unroll
        for (int u = 0; u < 4; u++) {
            int n = bn + lane + 32 * u;
            float v = acc[i][u];
            if (BIAS) v += bias[n];
            if (GELU) v = gelu_exact(v);
            C[(size_t)m * ldc + n] = v;
        }
    }
}

// ---------------- zero ----------------
__global__ void zero_agg_kernel() {
    int i = blockIdx.x * blockDim.x + threadIdx.x;
    if (i < TOK * DH) g_agg[i] = 0.f;
}

// ---------------- rowwise LayerNorm over 256: g_r = LN(g_agg) -------------
__global__ void __launch_bounds__(256) ln256_kernel(
    const float* __restrict__ g, const float* __restrict__ b)
{
    int t = blockIdx.x;
    int tid = threadIdx.x;
    int lane = tid & 31, wid = tid >> 5;
    float v = g_agg[t * DH + tid];
    float s1 = v, s2 = v * v;
#pragma unroll
    for (int o = 16; o; o >>= 1) {
        s1 += __shfl_xor_sync(~0u, s1, o);
        s2 += __shfl_xor_sync(~0u, s2, o);
    }
    __shared__ float r1[8], r2[8];
    if (lane == 0) { r1[wid] = s1; r2[wid] = s2; }
    __syncthreads();
    float t1 = 0.f, t2 = 0.f;
#pragma unroll
    for (int w = 0; w < 8; w++) { t1 += r1[w]; t2 += r2[w]; }
    float mean = t1 * (1.f / DH);
    float var = t2 * (1.f / DH) - mean * mean;
    float istd = rsqrtf(var + LN_EPS);
    g_r[t * DH + tid] = (v - mean) * istd * g[tid] + b[tid];
}

// ---------------- fused heavy stage ----------------
// For each (token t, neuron f): v = nv_proj[f,:] + a*w_act + b1 ;
// g = gelu(LN1(v)) ; y = g @ W2^T + b2 ; z = LN2(y) ; agg[t,:] += z
constexpr int FB  = 64;               // neurons per chunk
constexpr int CPB = 4;                // chunks per block
constexpr int BPT = (FF / FB) / CPB;  // 8 blocks per token
constexpr int SG_PITCH = FB + 1;      // 65
constexpr int SW_PITCH = DH + 1;      // 257
constexpr int SM_FLOATS = DH * SG_PITCH + 32 * SW_PITCH + 8 * DH + 7 * DH;
constexpr int SM_BYTES = SM_FLOATS * 4;  // 114,816 B

__global__ void __launch_bounds__(256) fused_main(
    const float* __restrict__ phi_w1, const float* __restrict__ phi_b1,
    const float* __restrict__ ln1g, const float* __restrict__ ln1b,
    const float* __restrict__ W2, const float* __restrict__ b2,
    const float* __restrict__ ln2g, const float* __restrict__ ln2b)
{
    extern __shared__ float sm[];
    float* sG    = sm;                      // [256 k][65] k-major G tile
    float* sW    = sG + DH * SG_PITCH;      // [32 kk][257] W2 k-tile
    float* sAgg  = sW + 32 * SW_PITCH;      // [8 warp][256]
    float* sWact = sAgg + 8 * DH;
    float* sB1   = sWact + DH;
    float* sL1g  = sB1 + DH;
    float* sL1b  = sL1g + DH;
    float* sB2   = sL1b + DH;
    float* sL2g  = sB2 + DH;
    float* sL2b  = sL2g + DH;

    int tid = threadIdx.x, lane = tid & 31, wid = tid >> 5;
    int t = blockIdx.x / BPT;
    int part = blockIdx.x % BPT;

    // per-k constants (256 threads, one each)
    sWact[tid] = phi_w1[tid * (DN + 1) + DN];  // last column of phi_w1
    sB1[tid]  = phi_b1[tid];
    sL1g[tid] = ln1g[tid];
    sL1b[tid] = ln1b[tid];
    sB2[tid]  = b2[tid];
    sL2g[tid] = ln2g[tid];
    sL2b[tid] = ln2b[tid];
    __syncthreads();

    float aggacc[8];
#pragma unroll
    for (int u = 0; u < 8; u++) aggacc[u] = 0.f;

    for (int cc = 0; cc < CPB; cc++) {
        int fbase = (part * CPB + cc) * FB;

        // ---- phase 1: build G tile (64 neurons x 256), warp wid owns 8 rows
#pragma unroll
        for (int nn = 0; nn < 8; nn++) {
            int fl = wid * 8 + nn;
            float a = g_acts[t * FF + fbase + fl];
            float v[8];
            float s1 = 0.f, s2 = 0.f;
#pragma unroll
            for (int q = 0; q < 8; q++) {
                int k = lane + 32 * q;
                float vv = g_nvproj[(size_t)(fbase + fl) * DH + k] + sB1[k] + a * sWact[k];
                v[q] = vv; s1 += vv; s2 += vv * vv;
            }
#pragma unroll
            for (int o = 16; o; o >>= 1) {
                s1 += __shfl_xor_sync(~0u, s1, o);
                s2 += __shfl_xor_sync(~0u, s2, o);
            }
            float mean = s1 * (1.f / DH);
            float var  = s2 * (1.f / DH) - mean * mean;
            float istd = rsqrtf(var + LN_EPS);
#pragma unroll
            for (int q = 0; q < 8; q++) {
                int k = lane + 32 * q;
                float x = (v[q] - mean) * istd * sL1g[k] + sL1b[k];
                sG[k * SG_PITCH + fl] = gelu_exact(x);
            }
        }
        __syncthreads();

        // ---- phase 2: Y(64x256) = G @ W2^T, thread tile 8f x 8j
        float acc[8][8];
#pragma unroll
        for (int i = 0; i < 8; i++)
#pragma unroll
            for (int u = 0; u < 8; u++) acc[i][u] = 0.f;

        for (int kt = 0; kt < DH / 32; kt++) {
#pragma unroll
            for (int r = 0; r < 32; r++) {
                int j = wid + 8 * r;
                sW[lane * SW_PITCH + j] = W2[(size_t)j * DH + kt * 32 + lane];
            }
            __syncthreads();
#pragma unroll
            for (int kk = 0; kk < 32; kk++) {
                float gr[8], wr[8];
#pragma unroll
                for (int i = 0; i < 8; i++) gr[i] = sG[(kt * 32 + kk) * SG_PITCH + wid * 8 + i];
#pragma unroll
                for (int u = 0; u < 8; u++) wr[u] = sW[kk * SW_PITCH + lane + 32 * u];
#pragma unroll
                for (int i = 0; i < 8; i++)
#pragma unroll
                    for (int u = 0; u < 8; u++) acc[i][u] += gr[i] * wr[u];
            }
            __syncthreads();
        }

        // ---- phase 3: +b2, LN2 per row (row f lives in warp wid), accumulate
#pragma unroll
        for (int i = 0; i < 8; i++) {
            float yv[8];
            float s1 = 0.f, s2 = 0.f;
#pragma unroll
            for (int u = 0; u < 8; u++) {
                int j = lane + 32 * u;
                float y = acc[i][u] + sB2[j];
                yv[u] = y; s1 += y; s2 += y * y;
            }
#pragma unroll
            for (int o = 16; o; o >>= 1) {
                s1 += __shfl_xor_sync(~0u, s1, o);
                s2 += __shfl_xor_sync(~0u, s2, o);
            }
            float mean = s1 * (1.f / DH);
            float var  = s2 * (1.f / DH) - mean * mean;
            float istd = rsqrtf(var + LN_EPS);
#pragma unroll
            for (int u = 0; u < 8; u++) {
                int j = lane + 32 * u;
                aggacc[u] += (yv[u] - mean) * istd * sL2g[j] + sL2b[j];
            }
        }
        __syncthreads();  // protect sG/sW for next chunk
    }

    // cross-warp reduction of agg partials, then one atomic per j
#pragma unroll
    for (int u = 0; u < 8; u++) sAgg[wid * DH + lane + 32 * u] = aggacc[u];
    __syncthreads();
    float s = 0.f;
#pragma unroll
    for (int w = 0; w < 8; w++) s += sAgg[w * DH + tid];
    atomicAdd(&g_agg[t * DH + tid], s);
}

// tiny trampolines so device-global scratch is referenced without host-side
// symbol lookups inside the capture path
__global__ void __launch_bounds__(256) gemm_acts(const float* __restrict__ x,
                                                 const float* __restrict__ W_in);
__global__ void __launch_bounds__(256) gemm_nvproj(const float* __restrict__ nv,
                                                   const float* __restrict__ phi_w1);

// acts = gelu(x @ W_in^T): reuse gemm_tn body via wrapper launches below is
// cleaner, but gemm_tn needs pointer args; pass device-global addresses from
// device side is impossible at launch. Instead: dedicated thin kernels that
// call an inlined common body.
template <bool GELU, bool BIAS>
__device__ __forceinline__ void gemm_tn_body(
    const float* __restrict__ A, int lda,
    const float* __restrict__ B, int ldb,
    const float* __restrict__ bias,
    float* __restrict__ C, int ldc, int K)
{
    constexpr int BM = 64, BN = 128, BK = 32;
    __shared__ float sA[BK][BM + 2];
    __shared__ float sB[BK][BN + 2];
    int tid = threadIdx.x;
    int lane = tid & 31, wid = tid >> 5;
    int bm = blockIdx.x * BM, bn = blockIdx.y * BN;

    float acc[8][4];
#pragma unroll
    for (int i = 0; i < 8; i++)
#pragma unroll
        for (int u = 0; u < 4; u++) acc[i][u] = 0.f;

    for (int k0 = 0; k0 < K; k0 += BK) {
#pragma unroll
        for (int r = 0; r < 8; r++) {
            int m = wid + 8 * r;
            sA[lane][m] = A[(size_t)(bm + m) * lda + k0 + lane];
        }
#pragma unroll
        for (int r = 0; r < 16; r++) {
            int n = wid + 8 * r;
            sB[lane][n] = B[(size_t)(bn + n) * ldb + k0 + lane];
        }
        __syncthreads();
#pragma unroll
        for (int kk = 0; kk < BK; kk++) {
            float a[8], b[4];
#pragma unroll
            for (int i = 0; i < 8; i++) a[i] = sA[kk][wid * 8 + i];
#pragma unroll
            for (int u = 0; u < 4; u++) b[u] = sB[kk][lane + 32 * u];
#pragma unroll
            for (int i = 0; i < 8; i++)
#pragma unroll
                for (int u = 0; u < 4; u++) acc[i][u] += a[i] * b[u];
        }
        __syncthreads();
    }
#pragma unroll
    for (int i = 0; i < 8; i++) {
        int m = bm + wid * 8 + i;
#pragma unroll
        for (int u = 0; u < 4; u++) {
            int n = bn + lane + 32 * u;
            float v = acc[i][u];
            if (BIAS) v += bias[n];
            if (GELU) v = gelu_exact(v);
            C[(size_t)m * ldc + n] = v;
        }
    }
}

__global__ void __launch_bounds__(256) gemm_acts(const float* __restrict__ x,
                                                 const float* __restrict__ W_in)
{   // acts = gelu(x @ W_in^T)  M=512 N=2048 K=512
    gemm_tn_body<true, false>(x, DMODEL, W_in, DMODEL, nullptr, g_acts, FF, DMODEL);
}

__global__ void __launch_bounds__(256) gemm_nvproj(const float* __restrict__ nv,
                                                   const float* __restrict__ phi_w1)
{   // nvproj = neuron_vecs @ w_nv^T  M=2048 N=256 K=128 (ldb=129 skips last col)
    gemm_tn_body<false, false>(nv, DN, phi_w1, DN + 1, nullptr, g_nvproj, DH, DN);
}

__global__ void __launch_bounds__(256) gemm_rho1(const float* __restrict__ rho_w1,
                                                 const float* __restrict__ rho_b1)
{   // r2 = gelu(r @ rho_w1^T + rho_b1)  M=512 N=512 K=256
    gemm_tn_body<true, true>(g_r, DH, rho_w1, DH, rho_b1, g_r2, DH2, DH);
}

__global__ void __launch_bounds__(256) gemm_rho2(const float* __restrict__ rho_w2,
                                                 const float* __restrict__ rho_b2,
                                                 float* __restrict__ out)
{   // out = r2 @ rho_w2^T + rho_b2  M=512 N=512 K=512
    gemm_tn_body<false, true>(g_r2, DH2, rho_w2, DH2, rho_b2, out, DMODEL, DH2);
}

// ---------------- launch ----------------
extern "C" void kernel_launch(void* const* d_in, const int* in_sizes, int n_in,
                              void* d_out, int out_size)
{
    const float* x      = (const float*)d_in[0];
    const float* nv     = (const float*)d_in[1];
    const float* W_in   = (const float*)d_in[2];
    const float* phi_w1 = (const float*)d_in[3];
    const float* phi_b1 = (const float*)d_in[4];
    const float* ln1g   = (const float*)d_in[5];
    const float* ln1b   = (const float*)d_in[6];
    const float* phi_w2 = (const float*)d_in[7];
    const float* phi_b2 = (const float*)d_in[8];
    const float* ln2g   = (const float*)d_in[9];
    const float* ln2b   = (const float*)d_in[10];
    const float* rln_g  = (const float*)d_in[11];
    const float* rln_b  = (const float*)d_in[12];
    const float* rho_w1 = (const float*)d_in[13];
    const float* rho_b1 = (const float*)d_in[14];
    const float* rho_w2 = (const float*)d_in[15];
    const float* rho_b2 = (const float*)d_in[16];
    float* out = (float*)d_out;

    gemm_acts<<<dim3(TOK / 64, FF / 128), 256>>>(x, W_in);
    gemm_nvproj<<<dim3(FF / 64, DH / 128), 256>>>(nv, phi_w1);
    zero_agg_kernel<<<(TOK * DH + 255) / 256, 256>>>();

    cudaFuncSetAttribute(fused_main, cudaFuncAttributeMaxDynamicSharedMemorySize, SM_BYTES);
    fused_main<<<TOK * BPT, 256, SM_BYTES>>>(
        phi_w1, phi_b1, ln1g, ln1b, phi_w2, phi_b2, ln2g, ln2b);

    ln256_kernel<<<TOK, 256>>>(rln_g, rln_b);
    gemm_rho1<<<dim3(TOK / 64, DH2 / 128), 256>>>(rho_w1, rho_b1);
    gemm_rho2<<<dim3(TOK / 64, DMODEL / 128), 256>>>(rho_w2, rho_b2, out);

    (void)in_sizes; (void)n_in; (void)out_size;
}

// round 4
// speedup vs baseline: 1.6970x; 1.6970x over previous
#include <cuda_runtime.h>
#include <cuda_bf16.h>
#include <math.h>
#include <stdint.h>

#define TOK 512
#define DMODEL 512
#define FF 2048
#define DN 128
#define DH 256
#define DH2 512
#define LN_EPS 1e-5f

// ---------------- scratch (no allocation allowed) ----------------
__device__ float g_acts[TOK * FF];
__device__ float g_nvproj[FF * DH];
__device__ float g_agg[TOK * DH];
__device__ float g_r[TOK * DH];
__device__ float g_r2[TOK * DH2];
// W2 split hi/lo, per 64-k chunk, padded rows of 72 bf16 (144B)
__device__ __align__(16) __nv_bfloat16 g_w2hi[4][256 * 72];
__device__ __align__(16) __nv_bfloat16 g_w2lo[4][256 * 72];
__device__ float4 g_fc[FF];   // per-f LN1 constants: mp, q0, q1
__device__ float g_wscal[2];  // mw, q2

__device__ __forceinline__ float gelu_exact(float x) {
    return 0.5f * x * (1.0f + erff(x * 0.70710678118654752440f));
}

__device__ __forceinline__ uint32_t smem_to_u32(const void* p) {
    uint32_t a;
    asm("{ .reg .u64 t; cvta.to.shared.u64 t, %1; cvt.u32.u64 %0, t; }"
        : "=r"(a) : "l"(p));
    return a;
}

__device__ __forceinline__ uint32_t pack_bf16(float e0, float e1) {
    uint32_t r;  // e0 -> low half, e1 -> high half
    asm("cvt.rn.bf16x2.f32 %0, %1, %2;" : "=r"(r) : "f"(e1), "f"(e0));
    return r;
}

#define LDSM_X4(r0, r1, r2, r3, addr) \
    asm volatile("ldmatrix.sync.aligned.m8n8.x4.shared.b16 {%0,%1,%2,%3}, [%4];" \
        : "=r"(r0), "=r"(r1), "=r"(r2), "=r"(r3) : "r"(addr))
#define LDSM_X2(r0, r1, addr) \
    asm volatile("ldmatrix.sync.aligned.m8n8.x2.shared.b16 {%0,%1}, [%2];" \
        : "=r"(r0), "=r"(r1) : "r"(addr))
#define MMA16816(d, a, b) \
    asm volatile("mma.sync.aligned.m16n8k16.row.col.f32.bf16.bf16.f32 " \
        "{%0,%1,%2,%3}, {%4,%5,%6,%7}, {%8,%9}, {%0,%1,%2,%3};" \
        : "+f"((d)[0]), "+f"((d)[1]), "+f"((d)[2]), "+f"((d)[3]) \
        : "r"((a)[0]), "r"((a)[1]), "r"((a)[2]), "r"((a)[3]), \
          "r"((b)[0]), "r"((b)[1]))

// ======================= generic SIMT GEMM (small stages) ==================
template <bool GELU, bool BIAS>
__device__ __forceinline__ void gemm_tn_body(
    const float* __restrict__ A, int lda,
    const float* __restrict__ B, int ldb,
    const float* __restrict__ bias,
    float* __restrict__ C, int ldc, int K)
{
    constexpr int BM = 64, BN = 128, BK = 32;
    __shared__ float sA[BK][BM + 2];
    __shared__ float sB[BK][BN + 2];
    int tid = threadIdx.x;
    int lane = tid & 31, wid = tid >> 5;
    int bm = blockIdx.x * BM, bn = blockIdx.y * BN;

    float acc[8][4];
#pragma unroll
    for (int i = 0; i < 8; i++)
#pragma unroll
        for (int u = 0; u < 4; u++) acc[i][u] = 0.f;

    for (int k0 = 0; k0 < K; k0 += BK) {
#pragma unroll
        for (int r = 0; r < 8; r++) {
            int m = wid + 8 * r;
            sA[lane][m] = A[(size_t)(bm + m) * lda + k0 + lane];
        }
#pragma unroll
        for (int r = 0; r < 16; r++) {
            int n = wid + 8 * r;
            sB[lane][n] = B[(size_t)(bn + n) * ldb + k0 + lane];
        }
        __syncthreads();
#pragma unroll
        for (int kk = 0; kk < BK; kk++) {
            float a[8], b[4];
#pragma unroll
            for (int i = 0; i < 8; i++) a[i] = sA[kk][wid * 8 + i];
#pragma unroll
            for (int u = 0; u < 4; u++) b[u] = sB[kk][lane + 32 * u];
#pragma unroll
            for (int i = 0; i < 8; i++)
#pragma unroll
                for (int u = 0; u < 4; u++) acc[i][u] += a[i] * b[u];
        }
        __syncthreads();
    }
#pragma unroll
    for (int i = 0; i < 8; i++) {
        int m = bm + wid * 8 + i;
#pragma unroll
        for (int u = 0; u < 4; u++) {
            int n = bn + lane + 32 * u;
            float v = acc[i][u];
            if (BIAS) v += bias[n];
            if (GELU) v = gelu_exact(v);
            C[(size_t)m * ldc + n] = v;
        }
    }
}

__global__ void __launch_bounds__(256) gemm_acts(const float* __restrict__ x,
                                                 const float* __restrict__ W_in)
{   gemm_tn_body<true, false>(x, DMODEL, W_in, DMODEL, nullptr, g_acts, FF, DMODEL); }

__global__ void __launch_bounds__(256) gemm_nvproj(const float* __restrict__ nv,
                                                   const float* __restrict__ phi_w1)
{   gemm_tn_body<false, false>(nv, DN, phi_w1, DN + 1, nullptr, g_nvproj, DH, DN); }

__global__ void __launch_bounds__(256) gemm_rho1(const float* __restrict__ rho_w1,
                                                 const float* __restrict__ rho_b1)
{   gemm_tn_body<true, true>(g_r, DH, rho_w1, DH, rho_b1, g_r2, DH2, DH); }

__global__ void __launch_bounds__(256) gemm_rho2(const float* __restrict__ rho_w2,
                                                 const float* __restrict__ rho_b2,
                                                 float* __restrict__ out)
{   gemm_tn_body<false, true>(g_r2, DH2, rho_w2, DH2, rho_b2, out, DMODEL, DH2); }

// ======================= prep kernels =======================
// W2 -> bf16 hi/lo, chunked by 64-k, rows padded to 72 bf16
__global__ void __launch_bounds__(256) prep_w2(const float* __restrict__ w2) {
    int idx = blockIdx.x * 256 + threadIdx.x;  // 65536 elems
    int j = idx >> 8, k = idx & 255;
    float w = w2[idx];
    __nv_bfloat16 hi = __float2bfloat16(w);
    __nv_bfloat16 lo = __float2bfloat16(w - __bfloat162float(hi));
    int kc = k >> 6, kin = k & 63;
    g_w2hi[kc][j * 72 + kin] = hi;
    g_w2lo[kc][j * 72 + kin] = lo;
}

// scalars over w_act: mw = mean(w), q2 = mean(w^2)
__global__ void __launch_bounds__(256) prep_scal(const float* __restrict__ phi_w1) {
    int tid = threadIdx.x, lane = tid & 31, wid = tid >> 5;
    float w = phi_w1[tid * (DN + 1) + DN];
    float s0 = w, s1 = w * w;
#pragma unroll
    for (int o = 16; o; o >>= 1) {
        s0 += __shfl_xor_sync(~0u, s0, o);
        s1 += __shfl_xor_sync(~0u, s1, o);
    }
    __shared__ float r0[8], r1[8];
    if (lane == 0) { r0[wid] = s0; r1[wid] = s1; }
    __syncthreads();
    if (tid == 0) {
        float t0 = 0.f, t1 = 0.f;
        for (int i = 0; i < 8; i++) { t0 += r0[i]; t1 += r1[i]; }
        g_wscal[0] = t0 * (1.f / DH);
        g_wscal[1] = t1 * (1.f / DH);
    }
}

// per-f LN1 constants: p = nvproj[f]+b1 : mp=mean(p), q0=mean(p^2), q1=mean(p*w)
__global__ void __launch_bounds__(256) prep_f(const float* __restrict__ phi_b1,
                                              const float* __restrict__ phi_w1) {
    int f = blockIdx.x;
    int tid = threadIdx.x, lane = tid & 31, wid = tid >> 5;
    float p = g_nvproj[f * DH + tid] + phi_b1[tid];
    float w = phi_w1[tid * (DN + 1) + DN];
    float s0 = p, s1 = p * p, s2 = p * w;
#pragma unroll
    for (int o = 16; o; o >>= 1) {
        s0 += __shfl_xor_sync(~0u, s0, o);
        s1 += __shfl_xor_sync(~0u, s1, o);
        s2 += __shfl_xor_sync(~0u, s2, o);
    }
    __shared__ float r0[8], r1[8], r2[8];
    if (lane == 0) { r0[wid] = s0; r1[wid] = s1; r2[wid] = s2; }
    __syncthreads();
    if (tid == 0) {
        float t0 = 0.f, t1 = 0.f, t2 = 0.f;
        for (int i = 0; i < 8; i++) { t0 += r0[i]; t1 += r1[i]; t2 += r2[i]; }
        g_fc[f] = make_float4(t0 * (1.f / DH), t1 * (1.f / DH), t2 * (1.f / DH), 0.f);
    }
}

__global__ void zero_agg_kernel() {
    int i = blockIdx.x * blockDim.x + threadIdx.x;
    if (i < TOK * DH) g_agg[i] = 0.f;
}

// ======================= fused warp-MMA heavy stage =====================
// block = (token, 128 neurons): M=128, N=256, K=256 chunked by 64.
// 8 warps: wm = wid&1 (m 64-band), wn = wid>>1 (n 64-band). Warp tile 64x64.
constexpr int CONST_B1   = 0;      // floats
constexpr int CONST_WACT = 256;
constexpr int CONST_L1G  = 512;
constexpr int CONST_L1B  = 768;
constexpr int CONST_B2   = 1024;
constexpr int CONST_L2G  = 1280;
constexpr int CONST_L2B  = 1536;
constexpr int CONST_RED1 = 1792;
constexpr int CONST_RED2 = 2048;
constexpr int TILE_OFF   = 9216;   // bytes
constexpr int A_HI_OFF   = TILE_OFF;
constexpr int A_LO_OFF   = TILE_OFF + 18432;
constexpr int B_HI_OFF   = TILE_OFF + 36864;
constexpr int B_LO_OFF   = TILE_OFF + 73728;
constexpr int Y_PITCH    = 258;    // floats
constexpr int SMEM_BYTES = TILE_OFF + 128 * Y_PITCH * 4;  // 9216 + 132096 = 141312

__global__ void __launch_bounds__(256, 1) fused_mma(
    const float* __restrict__ phi_b1, const float* __restrict__ phi_w1,
    const float* __restrict__ ln1g, const float* __restrict__ ln1b,
    const float* __restrict__ b2, const float* __restrict__ ln2g,
    const float* __restrict__ ln2b)
{
    extern __shared__ char smem[];
    float* sF = (float*)smem;
    const uint32_t sbase = smem_to_u32(smem);

    const int tid = threadIdx.x, lane = tid & 31, wid = tid >> 5;
    const int t = blockIdx.x >> 4;
    const int fbase = (blockIdx.x & 15) * 128;

    sF[CONST_B1 + tid]   = phi_b1[tid];
    sF[CONST_WACT + tid] = phi_w1[tid * (DN + 1) + DN];
    sF[CONST_L1G + tid]  = ln1g[tid];
    sF[CONST_L1B + tid]  = ln1b[tid];
    sF[CONST_B2 + tid]   = b2[tid];
    sF[CONST_L2G + tid]  = ln2g[tid];
    sF[CONST_L2B + tid]  = ln2b[tid];
    __syncthreads();

    // ---- per-row LN1 scalars (closed form); row shared by tid pairs ----
    const int row = tid >> 1;         // neuron row 0..127
    const int khalf = tid & 1;        // which 32-k half of each chunk
    const int f = fbase + row;
    const float a = g_acts[t * FF + f];
    const float4 fc = g_fc[f];
    const float mean = fc.x + a * g_wscal[0];
    const float e2 = fc.y + 2.f * a * fc.z + a * a * g_wscal[1];
    const float istd = rsqrtf(e2 - mean * mean + LN_EPS);

    const int wm = wid & 1, wn = wid >> 1;

    float acc[4][8][4];
#pragma unroll
    for (int mt = 0; mt < 4; mt++)
#pragma unroll
        for (int nt = 0; nt < 8; nt++)
#pragma unroll
            for (int i = 0; i < 4; i++) acc[mt][nt][i] = 0.f;

    // ldmatrix base addresses
    const uint32_t aHiBase = sbase + A_HI_OFF +
        (uint32_t)((wm * 64 + (lane & 15)) * 144 + (lane >> 4) * 16);
    const uint32_t aLoBase = aHiBase + 18432;
    const uint32_t bHiBase = sbase + B_HI_OFF +
        (uint32_t)((wn * 64 + (lane & 7)) * 144 + ((lane >> 3) & 1) * 16);
    const uint32_t bLoBase = bHiBase + 36864;

#pragma unroll 1
    for (int kc = 0; kc < 4; kc++) {
        // ---- copy W2 chunk hi/lo (padded layout, straight uint4) ----
        {
            const uint4* srcH = (const uint4*)(g_w2hi[kc]);
            const uint4* srcL = (const uint4*)(g_w2lo[kc]);
            uint4* dstH = (uint4*)(smem + B_HI_OFF);
            uint4* dstL = (uint4*)(smem + B_LO_OFF);
#pragma unroll
            for (int i = 0; i < 9; i++) {
                dstH[i * 256 + tid] = srcH[i * 256 + tid];
                dstL[i * 256 + tid] = srcL[i * 256 + tid];
            }
        }

        // ---- produce A chunk: this thread: row, k = kc*64 + khalf*32 + [0,32) ----
        {
            const float* nvp = g_nvproj + (size_t)f * DH + kc * 64 + khalf * 32;
            char* dstH = smem + A_HI_OFF + row * 144 + khalf * 64;
            char* dstL = smem + A_LO_OFF + row * 144 + khalf * 64;
#pragma unroll 2
            for (int u = 0; u < 8; u++) {
                float4 pv = *(const float4*)(nvp + u * 4);
                float gv[4];
                int kb = kc * 64 + khalf * 32 + u * 4;
                float p4[4] = {pv.x, pv.y, pv.z, pv.w};
#pragma unroll
                for (int e = 0; e < 4; e++) {
                    int k = kb + e;
                    float val = p4[e] + sF[CONST_B1 + k] + a * sF[CONST_WACT + k];
                    float xx = (val - mean) * istd * sF[CONST_L1G + k] + sF[CONST_L1B + k];
                    gv[e] = gelu_exact(xx);
                }
                uint32_t h0 = pack_bf16(gv[0], gv[1]);
                uint32_t h1 = pack_bf16(gv[2], gv[3]);
                float hf0 = __uint_as_float(h0 << 16);
                float hf1 = __uint_as_float(h0 & 0xFFFF0000u);
                float hf2 = __uint_as_float(h1 << 16);
                float hf3 = __uint_as_float(h1 & 0xFFFF0000u);
                uint32_t l0 = pack_bf16(gv[0] - hf0, gv[1] - hf1);
                uint32_t l1 = pack_bf16(gv[2] - hf2, gv[3] - hf3);
                *(uint2*)(dstH + u * 8) = make_uint2(h0, h1);
                *(uint2*)(dstL + u * 8) = make_uint2(l0, l1);
            }
        }
        __syncthreads();

        // ---- MMA over this 64-k chunk: 4 k16 steps, 3 passes each ----
#pragma unroll
        for (int k16 = 0; k16 < 4; k16++) {
            const uint32_t koff = k16 * 32;
            uint32_t ah[4][4], al[4][4], bb[8][2];
#pragma unroll
            for (int mt = 0; mt < 4; mt++)
                LDSM_X4(ah[mt][0], ah[mt][1], ah[mt][2], ah[mt][3],
                        aHiBase + mt * 2304 + koff);
#pragma unroll
            for (int mt = 0; mt < 4; mt++)
                LDSM_X4(al[mt][0], al[mt][1], al[mt][2], al[mt][3],
                        aLoBase + mt * 2304 + koff);
#pragma unroll
            for (int nt = 0; nt < 8; nt++)
                LDSM_X2(bb[nt][0], bb[nt][1], bHiBase + nt * 1152 + koff);
            // hi*Hi
#pragma unroll
            for (int mt = 0; mt < 4; mt++)
#pragma unroll
                for (int nt = 0; nt < 8; nt++)
                    MMA16816(acc[mt][nt], ah[mt], bb[nt]);
            // lo*Hi
#pragma unroll
            for (int mt = 0; mt < 4; mt++)
#pragma unroll
                for (int nt = 0; nt < 8; nt++)
                    MMA16816(acc[mt][nt], al[mt], bb[nt]);
            // hi*Lo
#pragma unroll
            for (int nt = 0; nt < 8; nt++)
                LDSM_X2(bb[nt][0], bb[nt][1], bLoBase + nt * 1152 + koff);
#pragma unroll
            for (int mt = 0; mt < 4; mt++)
#pragma unroll
                for (int nt = 0; nt < 8; nt++)
                    MMA16816(acc[mt][nt], ah[mt], bb[nt]);
        }
        __syncthreads();  // protect A/B tiles (and later sY) before overwrite
    }

    // ---- epilogue: stage Y to smem, LN2 per row, column-sum into agg ----
    float* sY = (float*)(smem + TILE_OFF);
    {
        const int r0 = wm * 64 + (lane >> 2);
        const int c0 = wn * 64 + (lane & 3) * 2;
#pragma unroll
        for (int mt = 0; mt < 4; mt++) {
#pragma unroll
            for (int nt = 0; nt < 8; nt++) {
                int rr = r0 + mt * 16;
                int cc = c0 + nt * 8;
                *(float2*)&sY[rr * Y_PITCH + cc] =
                    make_float2(acc[mt][nt][0], acc[mt][nt][1]);
                *(float2*)&sY[(rr + 8) * Y_PITCH + cc] =
                    make_float2(acc[mt][nt][2], acc[mt][nt][3]);
            }
        }
    }
    __syncthreads();

    // stats: thread handles half a row (row = tid&127, half = tid>>7)
    const int erow = tid & 127, ehalf = tid >> 7;
    {
        float s1 = 0.f, s2 = 0.f;
        const float* yr = sY + erow * Y_PITCH + ehalf * 128;
        const float* bb2 = sF + CONST_B2 + ehalf * 128;
#pragma unroll 8
        for (int j = 0; j < 128; j++) {
            float y = yr[j] + bb2[j];
            s1 += y; s2 += y * y;
        }
        sF[CONST_RED1 + tid] = s1;
        sF[CONST_RED2 + tid] = s2;
    }
    __syncthreads();
    {
        float s1 = sF[CONST_RED1 + tid] + sF[CONST_RED1 + (tid ^ 128)];
        float s2 = sF[CONST_RED2 + tid] + sF[CONST_RED2 + (tid ^ 128)];
        float mu = s1 * (1.f / DH);
        float vr = s2 * (1.f / DH) - mu * mu;
        float is2 = rsqrtf(vr + LN_EPS);
        float* yr = sY + erow * Y_PITCH + ehalf * 128;
        const float* bb2 = sF + CONST_B2 + ehalf * 128;
        const float* gg = sF + CONST_L2G + ehalf * 128;
        const float* bb = sF + CONST_L2B + ehalf * 128;
#pragma unroll 8
        for (int j = 0; j < 128; j++) {
            float y = yr[j] + bb2[j];
            yr[j] = (y - mu) * is2 * gg[j] + bb[j];
        }
    }
    __syncthreads();
    {
        float s = 0.f;
#pragma unroll 8
        for (int r = 0; r < 128; r++) s += sY[r * Y_PITCH + tid];
        atomicAdd(&g_agg[t * DH + tid], s);
    }
}

// ---------------- final LN over agg ----------------
__global__ void __launch_bounds__(256) ln256_kernel(
    const float* __restrict__ g, const float* __restrict__ b)
{
    int t = blockIdx.x;
    int tid = threadIdx.x;
    int lane = tid & 31, wid = tid >> 5;
    float v = g_agg[t * DH + tid];
    float s1 = v, s2 = v * v;
#pragma unroll
    for (int o = 16; o; o >>= 1) {
        s1 += __shfl_xor_sync(~0u, s1, o);
        s2 += __shfl_xor_sync(~0u, s2, o);
    }
    __shared__ float r1[8], r2[8];
    if (lane == 0) { r1[wid] = s1; r2[wid] = s2; }
    __syncthreads();
    float t1 = 0.f, t2 = 0.f;
#pragma unroll
    for (int w = 0; w < 8; w++) { t1 += r1[w]; t2 += r2[w]; }
    float mean = t1 * (1.f / DH);
    float var = t2 * (1.f / DH) - mean * mean;
    float istd = rsqrtf(var + LN_EPS);
    g_r[t * DH + tid] = (v - mean) * istd * g[tid] + b[tid];
}

// ---------------- launch ----------------
extern "C" void kernel_launch(void* const* d_in, const int* in_sizes, int n_in,
                              void* d_out, int out_size)
{
    const float* x      = (const float*)d_in[0];
    const float* nv     = (const float*)d_in[1];
    const float* W_in   = (const float*)d_in[2];
    const float* phi_w1 = (const float*)d_in[3];
    const float* phi_b1 = (const float*)d_in[4];
    const float* ln1g   = (const float*)d_in[5];
    const float* ln1b   = (const float*)d_in[6];
    const float* phi_w2 = (const float*)d_in[7];
    const float* phi_b2 = (const float*)d_in[8];
    const float* ln2g   = (const float*)d_in[9];
    const float* ln2b   = (const float*)d_in[10];
    const float* rln_g  = (const float*)d_in[11];
    const float* rln_b  = (const float*)d_in[12];
    const float* rho_w1 = (const float*)d_in[13];
    const float* rho_b1 = (const float*)d_in[14];
    const float* rho_w2 = (const float*)d_in[15];
    const float* rho_b2 = (const float*)d_in[16];
    float* out = (float*)d_out;

    gemm_acts<<<dim3(TOK / 64, FF / 128), 256>>>(x, W_in);
    gemm_nvproj<<<dim3(FF / 64, DH / 128), 256>>>(nv, phi_w1);
    prep_w2<<<256, 256>>>(phi_w2);
    prep_scal<<<1, 256>>>(phi_w1);
    prep_f<<<FF, 256>>>(phi_b1, phi_w1);
    zero_agg_kernel<<<(TOK * DH + 255) / 256, 256>>>();

    cudaFuncSetAttribute(fused_mma, cudaFuncAttributeMaxDynamicSharedMemorySize,
                         SMEM_BYTES);
    fused_mma<<<TOK * 16, 256, SMEM_BYTES>>>(phi_b1, phi_w1, ln1g, ln1b,
                                             phi_b2, ln2g, ln2b);

    ln256_kernel<<<TOK, 256>>>(rln_g, rln_b);
    gemm_rho1<<<dim3(TOK / 64, DH2 / 128), 256>>>(rho_w1, rho_b1);
    gemm_rho2<<<dim3(TOK / 64, DMODEL / 128), 256>>>(rho_w2, rho_b2, out);

    (void)in_sizes; (void)n_in; (void)out_size;
}

// round 5
// speedup vs baseline: 2.1282x; 1.2541x over previous
#include <cuda_runtime.h>
#include <cuda_bf16.h>
#include <math.h>
#include <stdint.h>

#define TOK 512
#define DMODEL 512
#define FF 2048
#define DN 128
#define DH 256
#define DH2 512
#define LN_EPS 1e-5f

// ---------------- scratch (no allocation allowed) ----------------
__device__ float g_acts[TOK * FF];
__device__ float g_nvproj[FF * DH];
__device__ float g_agg[TOK * DH];
__device__ float g_r[TOK * DH];
__device__ float g_r2[TOK * DH2];
// W2 split hi/lo, per 64-k chunk, padded rows of 72 bf16 (144B)
__device__ __align__(16) __nv_bfloat16 g_w2hi[4][256 * 72];
__device__ __align__(16) __nv_bfloat16 g_w2lo[4][256 * 72];
__device__ float4 g_fc[FF];   // per-f LN1 constants: mp, q0, q1
__device__ float g_wscal[2];  // mw, q2

__device__ __forceinline__ float gelu_exact(float x) {
    return 0.5f * x * (1.0f + erff(x * 0.70710678118654752440f));
}

__device__ __forceinline__ uint32_t smem_to_u32(const void* p) {
    uint32_t a;
    asm("{ .reg .u64 t; cvta.to.shared.u64 t, %1; cvt.u32.u64 %0, t; }"
        : "=r"(a) : "l"(p));
    return a;
}

__device__ __forceinline__ uint32_t pack_bf16(float e0, float e1) {
    uint32_t r;  // e0 -> low half, e1 -> high half
    asm("cvt.rn.bf16x2.f32 %0, %1, %2;" : "=r"(r) : "f"(e1), "f"(e0));
    return r;
}

#define LDSM_X4(r0, r1, r2, r3, addr) \
    asm volatile("ldmatrix.sync.aligned.m8n8.x4.shared.b16 {%0,%1,%2,%3}, [%4];" \
        : "=r"(r0), "=r"(r1), "=r"(r2), "=r"(r3) : "r"(addr))
#define LDSM_X2(r0, r1, addr) \
    asm volatile("ldmatrix.sync.aligned.m8n8.x2.shared.b16 {%0,%1}, [%2];" \
        : "=r"(r0), "=r"(r1) : "r"(addr))
#define MMA16816(d, a, b) \
    asm volatile("mma.sync.aligned.m16n8k16.row.col.f32.bf16.bf16.f32 " \
        "{%0,%1,%2,%3}, {%4,%5,%6,%7}, {%8,%9}, {%0,%1,%2,%3};" \
        : "+f"((d)[0]), "+f"((d)[1]), "+f"((d)[2]), "+f"((d)[3]) \
        : "r"((a)[0]), "r"((a)[1]), "r"((a)[2]), "r"((a)[3]), \
          "r"((b)[0]), "r"((b)[1]))
#define CP_ASYNC16(dst, src) \
    asm volatile("cp.async.cg.shared.global [%0], [%1], 16;" \
        :: "r"(dst), "l"(src) : "memory")
#define CP_COMMIT() asm volatile("cp.async.commit_group;" ::: "memory")
#define CP_WAIT(n)  asm volatile("cp.async.wait_group %0;" :: "n"(n) : "memory")

// ======================= generic SIMT GEMM (small stages) ==================
template <bool GELU, bool BIAS>
__device__ __forceinline__ void gemm_tn_body(
    const float* __restrict__ A, int lda,
    const float* __restrict__ B, int ldb,
    const float* __restrict__ bias,
    float* __restrict__ C, int ldc, int K)
{
    constexpr int BM = 64, BN = 128, BK = 32;
    __shared__ float sA[BK][BM + 2];
    __shared__ float sB[BK][BN + 2];
    int tid = threadIdx.x;
    int lane = tid & 31, wid = tid >> 5;
    int bm = blockIdx.x * BM, bn = blockIdx.y * BN;

    float acc[8][4];
#pragma unroll
    for (int i = 0; i < 8; i++)
#pragma unroll
        for (int u = 0; u < 4; u++) acc[i][u] = 0.f;

    for (int k0 = 0; k0 < K; k0 += BK) {
#pragma unroll
        for (int r = 0; r < 8; r++) {
            int m = wid + 8 * r;
            sA[lane][m] = A[(size_t)(bm + m) * lda + k0 + lane];
        }
#pragma unroll
        for (int r = 0; r < 16; r++) {
            int n = wid + 8 * r;
            sB[lane][n] = B[(size_t)(bn + n) * ldb + k0 + lane];
        }
        __syncthreads();
#pragma unroll
        for (int kk = 0; kk < BK; kk++) {
            float a[8], b[4];
#pragma unroll
            for (int i = 0; i < 8; i++) a[i] = sA[kk][wid * 8 + i];
#pragma unroll
            for (int u = 0; u < 4; u++) b[u] = sB[kk][lane + 32 * u];
#pragma unroll
            for (int i = 0; i < 8; i++)
#pragma unroll
                for (int u = 0; u < 4; u++) acc[i][u] += a[i] * b[u];
        }
        __syncthreads();
    }
#pragma unroll
    for (int i = 0; i < 8; i++) {
        int m = bm + wid * 8 + i;
#pragma unroll
        for (int u = 0; u < 4; u++) {
            int n = bn + lane + 32 * u;
            float v = acc[i][u];
            if (BIAS) v += bias[n];
            if (GELU) v = gelu_exact(v);
            C[(size_t)m * ldc + n] = v;
        }
    }
}

__global__ void __launch_bounds__(256) gemm_acts(const float* __restrict__ x,
                                                 const float* __restrict__ W_in)
{   gemm_tn_body<true, false>(x, DMODEL, W_in, DMODEL, nullptr, g_acts, FF, DMODEL); }

__global__ void __launch_bounds__(256) gemm_nvproj(const float* __restrict__ nv,
                                                   const float* __restrict__ phi_w1)
{   gemm_tn_body<false, false>(nv, DN, phi_w1, DN + 1, nullptr, g_nvproj, DH, DN); }

__global__ void __launch_bounds__(256) gemm_rho1(const float* __restrict__ rho_w1,
                                                 const float* __restrict__ rho_b1)
{   gemm_tn_body<true, true>(g_r, DH, rho_w1, DH, rho_b1, g_r2, DH2, DH); }

__global__ void __launch_bounds__(256) gemm_rho2(const float* __restrict__ rho_w2,
                                                 const float* __restrict__ rho_b2,
                                                 float* __restrict__ out)
{   gemm_tn_body<false, true>(g_r2, DH2, rho_w2, DH2, rho_b2, out, DMODEL, DH2); }

// ======================= prep kernels =======================
__global__ void __launch_bounds__(256) prep_w2(const float* __restrict__ w2) {
    int idx = blockIdx.x * 256 + threadIdx.x;  // 65536 elems
    int j = idx >> 8, k = idx & 255;
    float w = w2[idx];
    __nv_bfloat16 hi = __float2bfloat16(w);
    __nv_bfloat16 lo = __float2bfloat16(w - __bfloat162float(hi));
    int kc = k >> 6, kin = k & 63;
    g_w2hi[kc][j * 72 + kin] = hi;
    g_w2lo[kc][j * 72 + kin] = lo;
}

__global__ void __launch_bounds__(256) prep_scal(const float* __restrict__ phi_w1) {
    int tid = threadIdx.x, lane = tid & 31, wid = tid >> 5;
    float w = phi_w1[tid * (DN + 1) + DN];
    float s0 = w, s1 = w * w;
#pragma unroll
    for (int o = 16; o; o >>= 1) {
        s0 += __shfl_xor_sync(~0u, s0, o);
        s1 += __shfl_xor_sync(~0u, s1, o);
    }
    __shared__ float r0[8], r1[8];
    if (lane == 0) { r0[wid] = s0; r1[wid] = s1; }
    __syncthreads();
    if (tid == 0) {
        float t0 = 0.f, t1 = 0.f;
        for (int i = 0; i < 8; i++) { t0 += r0[i]; t1 += r1[i]; }
        g_wscal[0] = t0 * (1.f / DH);
        g_wscal[1] = t1 * (1.f / DH);
    }
}

__global__ void __launch_bounds__(256) prep_f(const float* __restrict__ phi_b1,
                                              const float* __restrict__ phi_w1) {
    int f = blockIdx.x;
    int tid = threadIdx.x, lane = tid & 31, wid = tid >> 5;
    float p = g_nvproj[f * DH + tid] + phi_b1[tid];
    float w = phi_w1[tid * (DN + 1) + DN];
    float s0 = p, s1 = p * p, s2 = p * w;
#pragma unroll
    for (int o = 16; o; o >>= 1) {
        s0 += __shfl_xor_sync(~0u, s0, o);
        s1 += __shfl_xor_sync(~0u, s1, o);
        s2 += __shfl_xor_sync(~0u, s2, o);
    }
    __shared__ float r0[8], r1[8], r2[8];
    if (lane == 0) { r0[wid] = s0; r1[wid] = s1; r2[wid] = s2; }
    __syncthreads();
    if (tid == 0) {
        float t0 = 0.f, t1 = 0.f, t2 = 0.f;
        for (int i = 0; i < 8; i++) { t0 += r0[i]; t1 += r1[i]; t2 += r2[i]; }
        g_fc[f] = make_float4(t0 * (1.f / DH), t1 * (1.f / DH), t2 * (1.f / DH), 0.f);
    }
}

__global__ void zero_agg_kernel() {
    int i = blockIdx.x * blockDim.x + threadIdx.x;
    if (i < TOK * DH) g_agg[i] = 0.f;
}

// ======================= fused warp-MMA heavy stage =====================
// block = (token, 128 neurons): M=128, N=256, K=256 chunked by 64.
// 8 warps: wm = wid&1, wn = wid>>1. Warp tile 64x64.
// smem float offsets
constexpr int CONST_B1   = 0;
constexpr int CONST_WACT = 256;
constexpr int CONST_L1G  = 512;
constexpr int CONST_L1B  = 768;
constexpr int CONST_B2   = 1024;
constexpr int CONST_L2G  = 1280;
constexpr int CONST_L2B  = 1536;
constexpr int SR1_OFF    = 1792;   // 512 floats: row stats s1 [128][4]
constexpr int SR2_OFF    = 2304;   // 512 floats
constexpr int SMU_OFF    = 2816;   // 128
constexpr int SIS_OFF    = 2944;   // 128
constexpr int SCOL_OFF   = 3072;   // 256
// byte offsets
constexpr int A_HI_OFF   = 13312;                  // 128 rows x 144B
constexpr int A_LO_OFF   = A_HI_OFF + 18432;
constexpr int B_OFF      = A_LO_OFF + 18432;       // 50176
constexpr int B_BUF      = 73728;                  // hi(36864)+lo(36864)
constexpr int SMEM_BYTES = B_OFF + 2 * B_BUF;      // 197632

__global__ void __launch_bounds__(256, 1) fused_mma(
    const float* __restrict__ phi_b1, const float* __restrict__ phi_w1,
    const float* __restrict__ ln1g, const float* __restrict__ ln1b,
    const float* __restrict__ b2, const float* __restrict__ ln2g,
    const float* __restrict__ ln2b)
{
    extern __shared__ char smem[];
    float* sF = (float*)smem;
    const uint32_t sbase = smem_to_u32(smem);

    const int tid = threadIdx.x, lane = tid & 31, wid = tid >> 5;
    const int t = blockIdx.x >> 4;
    const int fbase = (blockIdx.x & 15) * 128;

    // ---- prefetch B chunk 0 (cp.async) ----
    {
        uint32_t dstH = sbase + B_OFF + tid * 16;
        uint32_t dstL = dstH + 36864;
        const char* srcH = (const char*)g_w2hi[0] + tid * 16;
        const char* srcL = (const char*)g_w2lo[0] + tid * 16;
#pragma unroll
        for (int i = 0; i < 9; i++) {
            CP_ASYNC16(dstH + i * 4096, srcH + i * 4096);
            CP_ASYNC16(dstL + i * 4096, srcL + i * 4096);
        }
        CP_COMMIT();
    }

    sF[CONST_B1 + tid]   = phi_b1[tid];
    sF[CONST_WACT + tid] = phi_w1[tid * (DN + 1) + DN];
    sF[CONST_L1G + tid]  = ln1g[tid];
    sF[CONST_L1B + tid]  = ln1b[tid];
    sF[CONST_B2 + tid]   = b2[tid];
    sF[CONST_L2G + tid]  = ln2g[tid];
    sF[CONST_L2B + tid]  = ln2b[tid];
    sF[SCOL_OFF + tid]   = 0.f;
    __syncthreads();

    // ---- per-row LN1 scalars (closed form); row shared by tid pairs ----
    const int row = tid >> 1;        // neuron row 0..127
    const int khalf = tid & 1;       // which 32-k half of each chunk
    const int f = fbase + row;
    const float a = g_acts[t * FF + f];
    const float4 fc = g_fc[f];
    const float mean = fc.x + a * g_wscal[0];
    const float e2 = fc.y + 2.f * a * fc.z + a * a * g_wscal[1];
    const float istd = rsqrtf(e2 - mean * mean + LN_EPS);

    const int wm = wid & 1, wn = wid >> 1;

    float acc[4][8][4];
#pragma unroll
    for (int mt = 0; mt < 4; mt++)
#pragma unroll
        for (int nt = 0; nt < 8; nt++)
#pragma unroll
            for (int i = 0; i < 4; i++) acc[mt][nt][i] = 0.f;

    const uint32_t aHiBase = sbase + A_HI_OFF +
        (uint32_t)((wm * 64 + (lane & 15)) * 144 + (lane >> 4) * 16);
    const uint32_t aLoBase = aHiBase + 18432;
    const uint32_t bBase = sbase + B_OFF +
        (uint32_t)((wn * 64 + (lane & 7)) * 144 + ((lane >> 3) & 1) * 16);

#pragma unroll
    for (int kc = 0; kc < 4; kc++) {
        // ---- prefetch next B chunk ----
        if (kc < 3) {
            uint32_t dstH = sbase + B_OFF + ((kc + 1) & 1) * B_BUF + tid * 16;
            uint32_t dstL = dstH + 36864;
            const char* srcH = (const char*)g_w2hi[kc + 1] + tid * 16;
            const char* srcL = (const char*)g_w2lo[kc + 1] + tid * 16;
#pragma unroll
            for (int i = 0; i < 9; i++) {
                CP_ASYNC16(dstH + i * 4096, srcH + i * 4096);
                CP_ASYNC16(dstL + i * 4096, srcL + i * 4096);
            }
            CP_COMMIT();
        }

        // ---- produce A chunk (overlaps tensor execution of prior chunk) ----
        {
            const float* nvp = g_nvproj + (size_t)f * DH + kc * 64 + khalf * 32;
            char* dstH = smem + A_HI_OFF + row * 144 + khalf * 64;
            char* dstL = smem + A_LO_OFF + row * 144 + khalf * 64;
#pragma unroll 2
            for (int u = 0; u < 8; u++) {
                float4 pv = *(const float4*)(nvp + u * 4);
                float gv[4];
                int kb = kc * 64 + khalf * 32 + u * 4;
                float p4[4] = {pv.x, pv.y, pv.z, pv.w};
#pragma unroll
                for (int e = 0; e < 4; e++) {
                    int k = kb + e;
                    float val = p4[e] + sF[CONST_B1 + k] + a * sF[CONST_WACT + k];
                    float xx = (val - mean) * istd * sF[CONST_L1G + k] + sF[CONST_L1B + k];
                    gv[e] = gelu_exact(xx);
                }
                uint32_t h0 = pack_bf16(gv[0], gv[1]);
                uint32_t h1 = pack_bf16(gv[2], gv[3]);
                float hf0 = __uint_as_float(h0 << 16);
                float hf1 = __uint_as_float(h0 & 0xFFFF0000u);
                float hf2 = __uint_as_float(h1 << 16);
                float hf3 = __uint_as_float(h1 & 0xFFFF0000u);
                uint32_t l0 = pack_bf16(gv[0] - hf0, gv[1] - hf1);
                uint32_t l1 = pack_bf16(gv[2] - hf2, gv[3] - hf3);
                *(uint2*)(dstH + u * 8) = make_uint2(h0, h1);
                *(uint2*)(dstL + u * 8) = make_uint2(l0, l1);
            }
        }

        // ensure B(kc) landed (this thread), then cross-thread visibility
        if (kc < 3) { CP_WAIT(1); } else { CP_WAIT(0); }
        __syncthreads();

        // ---- MMA over this 64-k chunk: 4 k16 steps, 3 passes each ----
        const uint32_t bHiBase = bBase + (kc & 1) * B_BUF;
        const uint32_t bLoBase = bHiBase + 36864;
#pragma unroll
        for (int k16 = 0; k16 < 4; k16++) {
            const uint32_t koff = k16 * 32;
            uint32_t ah[4][4], al[4][4], bb[8][2];
#pragma unroll
            for (int mt = 0; mt < 4; mt++)
                LDSM_X4(ah[mt][0], ah[mt][1], ah[mt][2], ah[mt][3],
                        aHiBase + mt * 2304 + koff);
#pragma unroll
            for (int mt = 0; mt < 4; mt++)
                LDSM_X4(al[mt][0], al[mt][1], al[mt][2], al[mt][3],
                        aLoBase + mt * 2304 + koff);
#pragma unroll
            for (int nt = 0; nt < 8; nt++)
                LDSM_X2(bb[nt][0], bb[nt][1], bHiBase + nt * 1152 + koff);
#pragma unroll
            for (int mt = 0; mt < 4; mt++)
#pragma unroll
                for (int nt = 0; nt < 8; nt++)
                    MMA16816(acc[mt][nt], ah[mt], bb[nt]);
#pragma unroll
            for (int mt = 0; mt < 4; mt++)
#pragma unroll
                for (int nt = 0; nt < 8; nt++)
                    MMA16816(acc[mt][nt], al[mt], bb[nt]);
#pragma unroll
            for (int nt = 0; nt < 8; nt++)
                LDSM_X2(bb[nt][0], bb[nt][1], bLoBase + nt * 1152 + koff);
#pragma unroll
            for (int mt = 0; mt < 4; mt++)
#pragma unroll
                for (int nt = 0; nt < 8; nt++)
                    MMA16816(acc[mt][nt], ah[mt], bb[nt]);
        }
        __syncthreads();  // all ldmatrix(kc) done -> A/B(kc) buffers reusable
    }

    // ======== epilogue: fragment-resident LN2 + column sums ========
    // fragment cols for this thread: j = wn*64 + nt*8 + (lane&3)*2 + e
    float b2c[16], gc[16], bc[16];
#pragma unroll
    for (int nt = 0; nt < 8; nt++) {
        int j0 = wn * 64 + nt * 8 + (lane & 3) * 2;
        b2c[2 * nt]     = sF[CONST_B2 + j0];
        b2c[2 * nt + 1] = sF[CONST_B2 + j0 + 1];
        gc[2 * nt]      = sF[CONST_L2G + j0];
        gc[2 * nt + 1]  = sF[CONST_L2G + j0 + 1];
        bc[2 * nt]      = sF[CONST_L2B + j0];
        bc[2 * nt + 1]  = sF[CONST_L2B + j0 + 1];
    }

    // row stats (y = acc + b2), reduce over quad lanes, stash per-warp partials
#pragma unroll
    for (int mt = 0; mt < 4; mt++) {
#pragma unroll
        for (int h = 0; h < 2; h++) {
            float s1 = 0.f, s2 = 0.f;
#pragma unroll
            for (int nt = 0; nt < 8; nt++) {
                float y0 = acc[mt][nt][2 * h]     + b2c[2 * nt];
                float y1 = acc[mt][nt][2 * h + 1] + b2c[2 * nt + 1];
                acc[mt][nt][2 * h]     = y0;
                acc[mt][nt][2 * h + 1] = y1;
                s1 += y0 + y1;
                s2 += y0 * y0 + y1 * y1;
            }
            s1 += __shfl_xor_sync(~0u, s1, 1);
            s1 += __shfl_xor_sync(~0u, s1, 2);
            s2 += __shfl_xor_sync(~0u, s2, 1);
            s2 += __shfl_xor_sync(~0u, s2, 2);
            if ((lane & 3) == 0) {
                int r = wm * 64 + mt * 16 + (lane >> 2) + 8 * h;
                sF[SR1_OFF + r * 4 + wn] = s1;
                sF[SR2_OFF + r * 4 + wn] = s2;
            }
        }
    }
    __syncthreads();
    if (tid < 128) {
        float s1 = sF[SR1_OFF + tid * 4] + sF[SR1_OFF + tid * 4 + 1] +
                   sF[SR1_OFF + tid * 4 + 2] + sF[SR1_OFF + tid * 4 + 3];
        float s2 = sF[SR2_OFF + tid * 4] + sF[SR2_OFF + tid * 4 + 1] +
                   sF[SR2_OFF + tid * 4 + 2] + sF[SR2_OFF + tid * 4 + 3];
        float mu = s1 * (1.f / DH);
        float vr = s2 * (1.f / DH) - mu * mu;
        sF[SMU_OFF + tid] = mu;
        sF[SIS_OFF + tid] = rsqrtf(vr + LN_EPS);
    }
    __syncthreads();

    // normalize in regs + per-thread column partials
    float cs[16];
#pragma unroll
    for (int i = 0; i < 16; i++) cs[i] = 0.f;
#pragma unroll
    for (int mt = 0; mt < 4; mt++) {
#pragma unroll
        for (int h = 0; h < 2; h++) {
            int r = wm * 64 + mt * 16 + (lane >> 2) + 8 * h;
            float mu = sF[SMU_OFF + r];
            float is = sF[SIS_OFF + r];
#pragma unroll
            for (int nt = 0; nt < 8; nt++) {
#pragma unroll
                for (int e = 0; e < 2; e++) {
                    float z = (acc[mt][nt][2 * h + e] - mu) * is *
                              gc[2 * nt + e] + bc[2 * nt + e];
                    cs[2 * nt + e] += z;
                }
            }
        }
    }
    // reduce cols over the 8 row-lanes (bits 2..4 of lane)
#pragma unroll
    for (int i = 0; i < 16; i++) {
        cs[i] += __shfl_xor_sync(~0u, cs[i], 4);
        cs[i] += __shfl_xor_sync(~0u, cs[i], 8);
        cs[i] += __shfl_xor_sync(~0u, cs[i], 16);
    }
    if (lane < 4) {
#pragma unroll
        for (int nt = 0; nt < 8; nt++) {
#pragma unroll
            for (int e = 0; e < 2; e++) {
                int j = wn * 64 + nt * 8 + lane * 2 + e;
                atomicAdd(&sF[SCOL_OFF + j], cs[2 * nt + e]);
            }
        }
    }
    __syncthreads();
    atomicAdd(&g_agg[t * DH + tid], sF[SCOL_OFF + tid]);
}

// ---------------- final LN over agg ----------------
__global__ void __launch_bounds__(256) ln256_kernel(
    const float* __restrict__ g, const float* __restrict__ b)
{
    int t = blockIdx.x;
    int tid = threadIdx.x;
    int lane = tid & 31, wid = tid >> 5;
    float v = g_agg[t * DH + tid];
    float s1 = v, s2 = v * v;
#pragma unroll
    for (int o = 16; o; o >>= 1) {
        s1 += __shfl_xor_sync(~0u, s1, o);
        s2 += __shfl_xor_sync(~0u, s2, o);
    }
    __shared__ float r1[8], r2[8];
    if (lane == 0) { r1[wid] = s1; r2[wid] = s2; }
    __syncthreads();
    float t1 = 0.f, t2 = 0.f;
#pragma unroll
    for (int w = 0; w < 8; w++) { t1 += r1[w]; t2 += r2[w]; }
    float mean = t1 * (1.f / DH);
    float var = t2 * (1.f / DH) - mean * mean;
    float istd = rsqrtf(var + LN_EPS);
    g_r[t * DH + tid] = (v - mean) * istd * g[tid] + b[tid];
}

// ---------------- launch ----------------
extern "C" void kernel_launch(void* const* d_in, const int* in_sizes, int n_in,
                              void* d_out, int out_size)
{
    const float* x      = (const float*)d_in[0];
    const float* nv     = (const float*)d_in[1];
    const float* W_in   = (const float*)d_in[2];
    const float* phi_w1 = (const float*)d_in[3];
    const float* phi_b1 = (const float*)d_in[4];
    const float* ln1g   = (const float*)d_in[5];
    const float* ln1b   = (const float*)d_in[6];
    const float* phi_w2 = (const float*)d_in[7];
    const float* phi_b2 = (const float*)d_in[8];
    const float* ln2g   = (const float*)d_in[9];
    const float* ln2b   = (const float*)d_in[10];
    const float* rln_g  = (const float*)d_in[11];
    const float* rln_b  = (const float*)d_in[12];
    const float* rho_w1 = (const float*)d_in[13];
    const float* rho_b1 = (const float*)d_in[14];
    const float* rho_w2 = (const float*)d_in[15];
    const float* rho_b2 = (const float*)d_in[16];
    float* out = (float*)d_out;

    gemm_acts<<<dim3(TOK / 64, FF / 128), 256>>>(x, W_in);
    gemm_nvproj<<<dim3(FF / 64, DH / 128), 256>>>(nv, phi_w1);
    prep_w2<<<256, 256>>>(phi_w2);
    prep_scal<<<1, 256>>>(phi_w1);
    prep_f<<<FF, 256>>>(phi_b1, phi_w1);
    zero_agg_kernel<<<(TOK * DH + 255) / 256, 256>>>();

    cudaFuncSetAttribute(fused_mma, cudaFuncAttributeMaxDynamicSharedMemorySize,
                         SMEM_BYTES);
    fused_mma<<<TOK * 16, 256, SMEM_BYTES>>>(phi_b1, phi_w1, ln1g, ln1b,
                                             phi_b2, ln2g, ln2b);

    ln256_kernel<<<TOK, 256>>>(rln_g, rln_b);
    gemm_rho1<<<dim3(TOK / 64, DH2 / 128), 256>>>(rho_w1, rho_b1);
    gemm_rho2<<<dim3(TOK / 64, DMODEL / 128), 256>>>(rho_w2, rho_b2, out);

    (void)in_sizes; (void)n_in; (void)out_size;
}

// round 6
// speedup vs baseline: 3.2807x; 1.5415x over previous
#include <cuda_runtime.h>
#include <cuda_fp16.h>
#include <cuda_bf16.h>
#include <math.h>
#include <stdint.h>

#define TOK 512
#define DMODEL 512
#define FF 2048
#define DN 128
#define DH 256
#define DH2 512
#define LN_EPS 1e-5f

// ---------------- scratch (no allocation allowed) ----------------
__device__ float g_acts[TOK * FF];
__device__ float g_nvproj[FF * DH];
__device__ float g_agg[TOK * DH];
__device__ float g_r[TOK * DH];
__device__ float g_r2[TOK * DH2];
// W2 as fp16, per 64-k chunk, padded rows of 72 halves (144B)
__device__ __align__(16) __half g_w2f16[4][256 * 72];   // 147456 B total
__device__ float4 g_fc[FF];   // per-f LN1 constants: mp, q0, q1
__device__ float g_wscal[2];  // mw, q2

__device__ __forceinline__ float gelu_exact(float x) {
    return 0.5f * x * (1.0f + erff(x * 0.70710678118654752440f));
}

__device__ __forceinline__ uint32_t smem_to_u32(const void* p) {
    uint32_t a;
    asm("{ .reg .u64 t; cvta.to.shared.u64 t, %1; cvt.u32.u64 %0, t; }"
        : "=r"(a) : "l"(p));
    return a;
}

__device__ __forceinline__ uint32_t pack_f16(float e0, float e1) {
    uint32_t r;  // e0 -> low half, e1 -> high half
    asm("cvt.rn.f16x2.f32 %0, %1, %2;" : "=r"(r) : "f"(e1), "f"(e0));
    return r;
}

#define LDSM_X4(r0, r1, r2, r3, addr) \
    asm volatile("ldmatrix.sync.aligned.m8n8.x4.shared.b16 {%0,%1,%2,%3}, [%4];" \
        : "=r"(r0), "=r"(r1), "=r"(r2), "=r"(r3) : "r"(addr))
#define LDSM_X2(r0, r1, addr) \
    asm volatile("ldmatrix.sync.aligned.m8n8.x2.shared.b16 {%0,%1}, [%2];" \
        : "=r"(r0), "=r"(r1) : "r"(addr))
#define MMA16816F16(d, a, b) \
    asm volatile("mma.sync.aligned.m16n8k16.row.col.f32.f16.f16.f32 " \
        "{%0,%1,%2,%3}, {%4,%5,%6,%7}, {%8,%9}, {%0,%1,%2,%3};" \
        : "+f"((d)[0]), "+f"((d)[1]), "+f"((d)[2]), "+f"((d)[3]) \
        : "r"((a)[0]), "r"((a)[1]), "r"((a)[2]), "r"((a)[3]), \
          "r"((b)[0]), "r"((b)[1]))
#define CP_ASYNC16(dst, src) \
    asm volatile("cp.async.cg.shared.global [%0], [%1], 16;" \
        :: "r"(dst), "l"(src) : "memory")
#define CP_COMMIT() asm volatile("cp.async.commit_group;" ::: "memory")
#define CP_WAIT(n)  asm volatile("cp.async.wait_group %0;" :: "n"(n) : "memory")
#define NAMED_BAR(id) \
    asm volatile("bar.sync %0, 128;" :: "r"(id) : "memory")

// ======================= generic SIMT GEMM (small stages) ==================
template <bool GELU, bool BIAS>
__device__ __forceinline__ void gemm_tn_body(
    const float* __restrict__ A, int lda,
    const float* __restrict__ B, int ldb,
    const float* __restrict__ bias,
    float* __restrict__ C, int ldc, int K)
{
    constexpr int BM = 64, BN = 128, BK = 32;
    __shared__ float sA[BK][BM + 2];
    __shared__ float sB[BK][BN + 2];
    int tid = threadIdx.x;
    int lane = tid & 31, wid = tid >> 5;
    int bm = blockIdx.x * BM, bn = blockIdx.y * BN;

    float acc[8][4];
#pragma unroll
    for (int i = 0; i < 8; i++)
#pragma unroll
        for (int u = 0; u < 4; u++) acc[i][u] = 0.f;

    for (int k0 = 0; k0 < K; k0 += BK) {
#pragma unroll
        for (int r = 0; r < 8; r++) {
            int m = wid + 8 * r;
            sA[lane][m] = A[(size_t)(bm + m) * lda + k0 + lane];
        }
#pragma unroll
        for (int r = 0; r < 16; r++) {
            int n = wid + 8 * r;
            sB[lane][n] = B[(size_t)(bn + n) * ldb + k0 + lane];
        }
        __syncthreads();
#pragma unroll
        for (int kk = 0; kk < BK; kk++) {
            float a[8], b[4];
#pragma unroll
            for (int i = 0; i < 8; i++) a[i] = sA[kk][wid * 8 + i];
#pragma unroll
            for (int u = 0; u < 4; u++) b[u] = sB[kk][lane + 32 * u];
#pragma unroll
            for (int i = 0; i < 8; i++)
#pragma unroll
                for (int u = 0; u < 4; u++) acc[i][u] += a[i] * b[u];
        }
        __syncthreads();
    }
#pragma unroll
    for (int i = 0; i < 8; i++) {
        int m = bm + wid * 8 + i;
#pragma unroll
        for (int u = 0; u < 4; u++) {
            int n = bn + lane + 32 * u;
            float v = acc[i][u];
            if (BIAS) v += bias[n];
            if (GELU) v = gelu_exact(v);
            C[(size_t)m * ldc + n] = v;
        }
    }
}

__global__ void __launch_bounds__(256) gemm_acts(const float* __restrict__ x,
                                                 const float* __restrict__ W_in)
{   gemm_tn_body<true, false>(x, DMODEL, W_in, DMODEL, nullptr, g_acts, FF, DMODEL); }

__global__ void __launch_bounds__(256) gemm_nvproj(const float* __restrict__ nv,
                                                   const float* __restrict__ phi_w1)
{   gemm_tn_body<false, false>(nv, DN, phi_w1, DN + 1, nullptr, g_nvproj, DH, DN); }

__global__ void __launch_bounds__(256) gemm_rho1(const float* __restrict__ rho_w1,
                                                 const float* __restrict__ rho_b1)
{   gemm_tn_body<true, true>(g_r, DH, rho_w1, DH, rho_b1, g_r2, DH2, DH); }

__global__ void __launch_bounds__(256) gemm_rho2(const float* __restrict__ rho_w2,
                                                 const float* __restrict__ rho_b2,
                                                 float* __restrict__ out)
{   gemm_tn_body<false, true>(g_r2, DH2, rho_w2, DH2, rho_b2, out, DMODEL, DH2); }

// ======================= prep kernels =======================
__global__ void __launch_bounds__(256) prep_w2(const float* __restrict__ w2) {
    int idx = blockIdx.x * 256 + threadIdx.x;  // 65536 elems
    int j = idx >> 8, k = idx & 255;
    int kc = k >> 6, kin = k & 63;
    g_w2f16[kc][j * 72 + kin] = __float2half(w2[idx]);
}

__global__ void __launch_bounds__(256) prep_scal(const float* __restrict__ phi_w1) {
    int tid = threadIdx.x, lane = tid & 31, wid = tid >> 5;
    float w = phi_w1[tid * (DN + 1) + DN];
    float s0 = w, s1 = w * w;
#pragma unroll
    for (int o = 16; o; o >>= 1) {
        s0 += __shfl_xor_sync(~0u, s0, o);
        s1 += __shfl_xor_sync(~0u, s1, o);
    }
    __shared__ float r0[8], r1[8];
    if (lane == 0) { r0[wid] = s0; r1[wid] = s1; }
    __syncthreads();
    if (tid == 0) {
        float t0 = 0.f, t1 = 0.f;
        for (int i = 0; i < 8; i++) { t0 += r0[i]; t1 += r1[i]; }
        g_wscal[0] = t0 * (1.f / DH);
        g_wscal[1] = t1 * (1.f / DH);
    }
}

__global__ void __launch_bounds__(256) prep_f(const float* __restrict__ phi_b1,
                                              const float* __restrict__ phi_w1) {
    int f = blockIdx.x;
    int tid = threadIdx.x, lane = tid & 31, wid = tid >> 5;
    float p = g_nvproj[f * DH + tid] + phi_b1[tid];
    float w = phi_w1[tid * (DN + 1) + DN];
    float s0 = p, s1 = p * p, s2 = p * w;
#pragma unroll
    for (int o = 16; o; o >>= 1) {
        s0 += __shfl_xor_sync(~0u, s0, o);
        s1 += __shfl_xor_sync(~0u, s1, o);
        s2 += __shfl_xor_sync(~0u, s2, o);
    }
    __shared__ float r0[8], r1[8], r2[8];
    if (lane == 0) { r0[wid] = s0; r1[wid] = s1; r2[wid] = s2; }
    __syncthreads();
    if (tid == 0) {
        float t0 = 0.f, t1 = 0.f, t2 = 0.f;
        for (int i = 0; i < 8; i++) { t0 += r0[i]; t1 += r1[i]; t2 += r2[i]; }
        g_fc[f] = make_float4(t0 * (1.f / DH), t1 * (1.f / DH), t2 * (1.f / DH), 0.f);
    }
}

__global__ void zero_agg_kernel() {
    int i = blockIdx.x * blockDim.x + threadIdx.x;
    if (i < TOK * DH) g_agg[i] = 0.f;
}

// ======================= fused warp-MMA heavy stage =====================
// block = (token, 128 neurons). Two independent 4-warp groups (M=64 each),
// N=256, K=256 in 4x64 chunks. fp16 single-pass MMA. Whole W2 resident in smem.
// Groups sync only via named barriers -> produce(FMA) overlaps MMA(tensor).
constexpr int CONST_B1   = 0;      // float offsets
constexpr int CONST_WACT = 256;
constexpr int CONST_L1G  = 512;
constexpr int CONST_L1B  = 768;
constexpr int CONST_B2   = 1024;
constexpr int CONST_L2G  = 1280;
constexpr int CONST_L2B  = 1536;
constexpr int SR1_OFF    = 1792;   // [2 groups][64 rows][4 warps]
constexpr int SR2_OFF    = 2304;
constexpr int SMU_OFF    = 2816;   // [2][64]
constexpr int SIS_OFF    = 2944;
// byte offsets
constexpr int A_OFF      = 12288;               // 2 groups x 64 rows x 144B
constexpr int B_OFF      = A_OFF + 18432;       // 30720
constexpr int B_CHUNK    = 36864;               // 256 rows x 144B
constexpr int SMEM_BYTES = B_OFF + 4 * B_CHUNK; // 178176

__global__ void __launch_bounds__(256, 1) fused_mma(
    const float* __restrict__ phi_b1, const float* __restrict__ phi_w1,
    const float* __restrict__ ln1g, const float* __restrict__ ln1b,
    const float* __restrict__ b2, const float* __restrict__ ln2g,
    const float* __restrict__ ln2b)
{
    extern __shared__ char smem[];
    float* sF = (float*)smem;
    const uint32_t sbase = smem_to_u32(smem);

    const int tid = threadIdx.x, lane = tid & 31, wid = tid >> 5;
    const int t = blockIdx.x >> 4;
    const int fbase = (blockIdx.x & 15) * 128;

    // ---- async-load the WHOLE W2 (fp16, 144KB) once ----
    {
        uint32_t dst = sbase + B_OFF + tid * 16;
        const char* src = (const char*)g_w2f16 + tid * 16;
#pragma unroll
        for (int i = 0; i < 36; i++)
            CP_ASYNC16(dst + i * 4096, src + i * 4096);
        CP_COMMIT();
    }

    sF[CONST_B1 + tid]   = phi_b1[tid];
    sF[CONST_WACT + tid] = phi_w1[tid * (DN + 1) + DN];
    sF[CONST_L1G + tid]  = ln1g[tid];
    sF[CONST_L1B + tid]  = ln1b[tid];
    sF[CONST_B2 + tid]   = b2[tid];
    sF[CONST_L2G + tid]  = ln2g[tid];
    sF[CONST_L2B + tid]  = ln2b[tid];
    __syncthreads();

    // group structure: g = wid>>2 (M band), wn = wid&3 (N band)
    const int g = wid >> 2, wn = wid & 3;
    const int wg_tid = tid & 127;
    const int barid = 1 + g;

    // produce mapping: thread -> (row, 32-k half)
    const int row = wg_tid >> 1;
    const int khalf = wg_tid & 1;
    const int f = fbase + g * 64 + row;
    const float a = g_acts[t * FF + f];
    const float4 fc = g_fc[f];
    const float mean = fc.x + a * g_wscal[0];
    const float e2 = fc.y + 2.f * a * fc.z + a * a * g_wscal[1];
    const float istd = rsqrtf(e2 - mean * mean + LN_EPS);

    char* const aDst = smem + A_OFF + g * 9216 + row * 144 + khalf * 64;
    const float* const nvRow = g_nvproj + (size_t)f * DH + khalf * 32;

    // A producer for chunk kc (this thread's 32 values)
    auto produce = [&](int kc) {
        const float* nvp = nvRow + kc * 64;
#pragma unroll 2
        for (int u = 0; u < 8; u++) {
            float4 pv = *(const float4*)(nvp + u * 4);
            float p4[4] = {pv.x, pv.y, pv.z, pv.w};
            float gv[4];
            int kb = kc * 64 + khalf * 32 + u * 4;
#pragma unroll
            for (int e = 0; e < 4; e++) {
                int k = kb + e;
                float val = p4[e] + sF[CONST_B1 + k] + a * sF[CONST_WACT + k];
                float xx = (val - mean) * istd * sF[CONST_L1G + k] + sF[CONST_L1B + k];
                gv[e] = gelu_exact(xx);
            }
            *(uint2*)(aDst + u * 8) =
                make_uint2(pack_f16(gv[0], gv[1]), pack_f16(gv[2], gv[3]));
        }
    };

    float acc[4][8][4];
#pragma unroll
    for (int mt = 0; mt < 4; mt++)
#pragma unroll
        for (int nt = 0; nt < 8; nt++)
#pragma unroll
            for (int i = 0; i < 4; i++) acc[mt][nt][i] = 0.f;

    const uint32_t aBase = sbase + A_OFF + g * 9216 +
        (uint32_t)((lane & 15) * 144 + (lane >> 4) * 16);
    const uint32_t bBase = sbase + B_OFF +
        (uint32_t)((wn * 64 + (lane & 7)) * 144 + ((lane >> 3) & 1) * 16);

    auto mma_chunk = [&](int kc) {
        const uint32_t bC = bBase + kc * B_CHUNK;
#pragma unroll
        for (int k16 = 0; k16 < 4; k16++) {
            const uint32_t koff = k16 * 32;
            uint32_t ah[4][4], bb[8][2];
#pragma unroll
            for (int mt = 0; mt < 4; mt++)
                LDSM_X4(ah[mt][0], ah[mt][1], ah[mt][2], ah[mt][3],
                        aBase + mt * 2304 + koff);
#pragma unroll
            for (int nt = 0; nt < 8; nt++)
                LDSM_X2(bb[nt][0], bb[nt][1], bC + nt * 1152 + koff);
#pragma unroll
            for (int mt = 0; mt < 4; mt++)
#pragma unroll
                for (int nt = 0; nt < 8; nt++)
                    MMA16816F16(acc[mt][nt], ah[mt], bb[nt]);
        }
    };

    // chunk 0: produce, then block-wide sync (B landed + A0 visible)
    produce(0);
    CP_WAIT(0);
    __syncthreads();
    mma_chunk(0);
#pragma unroll
    for (int kc = 1; kc < 4; kc++) {
        NAMED_BAR(barid);   // group done reading A(kc-1)
        produce(kc);
        NAMED_BAR(barid);   // A(kc) visible to group
        mma_chunk(kc);
    }

    // ======== epilogue (group-local): LN2 in fragments + column sums ========
    float b2c[16], gc[16], bc[16];
#pragma unroll
    for (int nt = 0; nt < 8; nt++) {
        int j0 = wn * 64 + nt * 8 + (lane & 3) * 2;
        b2c[2 * nt]     = sF[CONST_B2 + j0];
        b2c[2 * nt + 1] = sF[CONST_B2 + j0 + 1];
        gc[2 * nt]      = sF[CONST_L2G + j0];
        gc[2 * nt + 1]  = sF[CONST_L2G + j0 + 1];
        bc[2 * nt]      = sF[CONST_L2B + j0];
        bc[2 * nt + 1]  = sF[CONST_L2B + j0 + 1];
    }

    // row stats: y = acc + b2; reduce over quad lanes; per-warp partials
#pragma unroll
    for (int mt = 0; mt < 4; mt++) {
#pragma unroll
        for (int h = 0; h < 2; h++) {
            float s1 = 0.f, s2 = 0.f;
#pragma unroll
            for (int nt = 0; nt < 8; nt++) {
                float y0 = acc[mt][nt][2 * h]     + b2c[2 * nt];
                float y1 = acc[mt][nt][2 * h + 1] + b2c[2 * nt + 1];
                acc[mt][nt][2 * h]     = y0;
                acc[mt][nt][2 * h + 1] = y1;
                s1 += y0 + y1;
                s2 += y0 * y0 + y1 * y1;
            }
            s1 += __shfl_xor_sync(~0u, s1, 1);
            s1 += __shfl_xor_sync(~0u, s1, 2);
            s2 += __shfl_xor_sync(~0u, s2, 1);
            s2 += __shfl_xor_sync(~0u, s2, 2);
            if ((lane & 3) == 0) {
                int r = mt * 16 + (lane >> 2) + 8 * h;  // 0..63 within group
                sF[SR1_OFF + g * 256 + r * 4 + wn] = s1;
                sF[SR2_OFF + g * 256 + r * 4 + wn] = s2;
            }
        }
    }
    NAMED_BAR(barid);
    if (wg_tid < 64) {
        int base = SR1_OFF + g * 256 + wg_tid * 4;
        float s1 = sF[base] + sF[base + 1] + sF[base + 2] + sF[base + 3];
        int base2 = SR2_OFF + g * 256 + wg_tid * 4;
        float s2 = sF[base2] + sF[base2 + 1] + sF[base2 + 2] + sF[base2 + 3];
        float mu = s1 * (1.f / DH);
        float vr = s2 * (1.f / DH) - mu * mu;
        sF[SMU_OFF + g * 64 + wg_tid] = mu;
        sF[SIS_OFF + g * 64 + wg_tid] = rsqrtf(vr + LN_EPS);
    }
    NAMED_BAR(barid);

    // normalize in regs + per-thread column partials
    float cs[16];
#pragma unroll
    for (int i = 0; i < 16; i++) cs[i] = 0.f;
#pragma unroll
    for (int mt = 0; mt < 4; mt++) {
#pragma unroll
        for (int h = 0; h < 2; h++) {
            int r = mt * 16 + (lane >> 2) + 8 * h;
            float mu = sF[SMU_OFF + g * 64 + r];
            float is = sF[SIS_OFF + g * 64 + r];
#pragma unroll
            for (int nt = 0; nt < 8; nt++) {
#pragma unroll
                for (int e = 0; e < 2; e++) {
                    cs[2 * nt + e] += (acc[mt][nt][2 * h + e] - mu) * is *
                                      gc[2 * nt + e] + bc[2 * nt + e];
                }
            }
        }
    }
    // reduce over the 8 row-lanes (lane bits 2..4)
#pragma unroll
    for (int i = 0; i < 16; i++) {
        cs[i] += __shfl_xor_sync(~0u, cs[i], 4);
        cs[i] += __shfl_xor_sync(~0u, cs[i], 8);
        cs[i] += __shfl_xor_sync(~0u, cs[i], 16);
    }
    if (lane < 4) {
        float* aggp = &g_agg[t * DH];
#pragma unroll
        for (int nt = 0; nt < 8; nt++) {
#pragma unroll
            for (int e = 0; e < 2; e++) {
                int j = wn * 64 + nt * 8 + lane * 2 + e;
                atomicAdd(aggp + j, cs[2 * nt + e]);
            }
        }
    }
}

// ---------------- final LN over agg ----------------
__global__ void __launch_bounds__(256) ln256_kernel(
    const float* __restrict__ g, const float* __restrict__ b)
{
    int t = blockIdx.x;
    int tid = threadIdx.x;
    int lane = tid & 31, wid = tid >> 5;
    float v = g_agg[t * DH + tid];
    float s1 = v, s2 = v * v;
#pragma unroll
    for (int o = 16; o; o >>= 1) {
        s1 += __shfl_xor_sync(~0u, s1, o);
        s2 += __shfl_xor_sync(~0u, s2, o);
    }
    __shared__ float r1[8], r2[8];
    if (lane == 0) { r1[wid] = s1; r2[wid] = s2; }
    __syncthreads();
    float t1 = 0.f, t2 = 0.f;
#pragma unroll
    for (int w = 0; w < 8; w++) { t1 += r1[w]; t2 += r2[w]; }
    float mean = t1 * (1.f / DH);
    float var = t2 * (1.f / DH) - mean * mean;
    float istd = rsqrtf(var + LN_EPS);
    g_r[t * DH + tid] = (v - mean) * istd * g[tid] + b[tid];
}

// ---------------- launch ----------------
extern "C" void kernel_launch(void* const* d_in, const int* in_sizes, int n_in,
                              void* d_out, int out_size)
{
    const float* x      = (const float*)d_in[0];
    const float* nv     = (const float*)d_in[1];
    const float* W_in   = (const float*)d_in[2];
    const float* phi_w1 = (const float*)d_in[3];
    const float* phi_b1 = (const float*)d_in[4];
    const float* ln1g   = (const float*)d_in[5];
    const float* ln1b   = (const float*)d_in[6];
    const float* phi_w2 = (const float*)d_in[7];
    const float* phi_b2 = (const float*)d_in[8];
    const float* ln2g   = (const float*)d_in[9];
    const float* ln2b   = (const float*)d_in[10];
    const float* rln_g  = (const float*)d_in[11];
    const float* rln_b  = (const float*)d_in[12];
    const float* rho_w1 = (const float*)d_in[13];
    const float* rho_b1 = (const float*)d_in[14];
    const float* rho_w2 = (const float*)d_in[15];
    const float* rho_b2 = (const float*)d_in[16];
    float* out = (float*)d_out;

    gemm_acts<<<dim3(TOK / 64, FF / 128), 256>>>(x, W_in);
    gemm_nvproj<<<dim3(FF / 64, DH / 128), 256>>>(nv, phi_w1);
    prep_w2<<<256, 256>>>(phi_w2);
    prep_scal<<<1, 256>>>(phi_w1);
    prep_f<<<FF, 256>>>(phi_b1, phi_w1);
    zero_agg_kernel<<<(TOK * DH + 255) / 256, 256>>>();

    cudaFuncSetAttribute(fused_mma, cudaFuncAttributeMaxDynamicSharedMemorySize,
                         SMEM_BYTES);
    fused_mma<<<TOK * 16, 256, SMEM_BYTES>>>(phi_b1, phi_w1, ln1g, ln1b,
                                             phi_b2, ln2g, ln2b);

    ln256_kernel<<<TOK, 256>>>(rln_g, rln_b);
    gemm_rho1<<<dim3(TOK / 64, DH2 / 128), 256>>>(rho_w1, rho_b1);
    gemm_rho2<<<dim3(TOK / 64, DMODEL / 128), 256>>>(rho_w2, rho_b2, out);

    (void)in_sizes; (void)n_in; (void)out_size;
}